// round 2
// baseline (speedup 1.0000x reference)
#include <cuda_runtime.h>
#include <cstdint>

// Problem constants (fixed shapes per reference setup_inputs)
#define BATCH    32
#define CH       64
#define HW       4096          // 64*64
#define NPIX     131072        // BATCH*HW
#define NCODE    1024
#define PPC      128           // pixels per CTA
#define CHUNK    64            // codes per chunk
#define NCHUNK   (NCODE / CHUNK)
#define ES_STRIDE 68           // padded row stride for Es (multiple of 4 for float4)
#define MARGIN   1e-2f         // top-2 gap below which we re-check in double
#define FIX_CAP  32768

#define XQ_ELEMS  (NPIX * CH)  // 8388608
#define IDX_ELEMS NPIX         // 131072

// Scratch (device globals — no allocation allowed)
__device__ float              g_e2[NCODE];
__device__ int                g_counts[NCODE];
__device__ unsigned long long g_loss_sum;
__device__ int                g_fix_cnt;
__device__ int                g_fix_list[FIX_CAP];

// ---------------------------------------------------------------------------
// Prep: ||e||^2 per code, zero histogram + loss accumulator + fix list
// ---------------------------------------------------------------------------
__global__ void vq_prep(const float* __restrict__ emb) {
    int c = blockIdx.x * blockDim.x + threadIdx.x;
    if (c < NCODE) {
        const float* row = emb + c * CH;
        float s = 0.f;
        #pragma unroll
        for (int k = 0; k < CH; k++) s = fmaf(row[k], row[k], s);
        g_e2[c]     = s;
        g_counts[c] = 0;
    }
    if (c == 0) { g_loss_sum = 0ull; g_fix_cnt = 0; }
}

// ---------------------------------------------------------------------------
// Main: distance argmin (top-2 tracked) + quantized write + idx + loss/counts
//   Thread layout: 16 tx (codes) x 16 ty (pixels), 8 pixels x 4 codes / thread
// ---------------------------------------------------------------------------
extern __shared__ float s_dyn[];   // Xs[64][128] then Es[64][ES_STRIDE]

__global__ __launch_bounds__(256) void vq_main(
        const float* __restrict__ x_in,
        const float* __restrict__ emb,
        float* __restrict__ out_xq,
        float* __restrict__ out_idx)
{
    float* Xs = s_dyn;                 // [CH][PPC]
    float* Es = s_dyn + CH * PPC;      // [CH][ES_STRIDE]

    __shared__ float e2s[CHUNK];
    __shared__ float x2s[PPC];
    __shared__ int   ridx[PPC];
    __shared__ float rloss[16];

    const int t  = threadIdx.x;
    const int tx = t & 15;
    const int ty = t >> 4;
    const int b  = blockIdx.x >> 5;            // 32 CTAs per image (4096/128)
    const int hw = (blockIdx.x & 31) * PPC;
    const int pbase = blockIdx.x * PPC;

    // ---- load X tile: 64 channels x 128 pixels, coalesced float4 ----
    {
        #pragma unroll
        for (int r = 0; r < 8; r++) {
            int e  = r * 256 + t;              // float4 id 0..2047
            int c  = e >> 5;                   // 32 float4 per channel row
            int p4 = e & 31;
            float4 v = *(const float4*)(x_in + (b * CH + c) * HW + hw + p4 * 4);
            *(float4*)(Xs + c * PPC + p4 * 4) = v;
        }
    }
    __syncthreads();

    // ---- per-pixel ||x||^2 ----
    if (t < PPC) {
        float s = 0.f;
        #pragma unroll
        for (int k = 0; k < CH; k++) { float v = Xs[k * PPC + t]; s = fmaf(v, v, s); }
        x2s[t] = s;
    }

    float minv[8], min2[8];
    int   mini[8];
    #pragma unroll
    for (int i = 0; i < 8; i++) { minv[i] = 3.4e38f; min2[i] = 3.4e38f; mini[i] = 0; }

    for (int chnk = 0; chnk < NCHUNK; chnk++) {
        __syncthreads();   // also covers x2s write on first iter, Es reuse after

        // ---- load codebook chunk transposed: Es[k][cc] = emb[chunk*64+cc][k]
        {
            int cc = t >> 2;                   // 0..63
            int kb = (t & 3) * 16;             // 0,16,32,48
            const float* er = emb + (chnk * CHUNK + cc) * CH + kb;
            float4 v0 = *(const float4*)(er + 0);
            float4 v1 = *(const float4*)(er + 4);
            float4 v2 = *(const float4*)(er + 8);
            float4 v3 = *(const float4*)(er + 12);
            Es[(kb + 0) * ES_STRIDE + cc] = v0.x;  Es[(kb + 1) * ES_STRIDE + cc] = v0.y;
            Es[(kb + 2) * ES_STRIDE + cc] = v0.z;  Es[(kb + 3) * ES_STRIDE + cc] = v0.w;
            Es[(kb + 4) * ES_STRIDE + cc] = v1.x;  Es[(kb + 5) * ES_STRIDE + cc] = v1.y;
            Es[(kb + 6) * ES_STRIDE + cc] = v1.z;  Es[(kb + 7) * ES_STRIDE + cc] = v1.w;
            Es[(kb + 8) * ES_STRIDE + cc] = v2.x;  Es[(kb + 9) * ES_STRIDE + cc] = v2.y;
            Es[(kb +10) * ES_STRIDE + cc] = v2.z;  Es[(kb +11) * ES_STRIDE + cc] = v2.w;
            Es[(kb +12) * ES_STRIDE + cc] = v3.x;  Es[(kb +13) * ES_STRIDE + cc] = v3.y;
            Es[(kb +14) * ES_STRIDE + cc] = v3.z;  Es[(kb +15) * ES_STRIDE + cc] = v3.w;
            if (t < CHUNK) e2s[t] = g_e2[chnk * CHUNK + t];
        }
        __syncthreads();

        // ---- register-tiled dot products: 8 pixels x 4 codes ----
        float acc[8][4];
        #pragma unroll
        for (int i = 0; i < 8; i++)
            #pragma unroll
            for (int j = 0; j < 4; j++) acc[i][j] = 0.f;

        #pragma unroll 8
        for (int k = 0; k < CH; k++) {
            float4 xa = *(const float4*)(Xs + k * PPC + ty * 8);
            float4 xb = *(const float4*)(Xs + k * PPC + ty * 8 + 4);
            float4 ev = *(const float4*)(Es + k * ES_STRIDE + tx * 4);
            float xv[8] = {xa.x, xa.y, xa.z, xa.w, xb.x, xb.y, xb.z, xb.w};
            float ee[4] = {ev.x, ev.y, ev.z, ev.w};
            #pragma unroll
            for (int i = 0; i < 8; i++)
                #pragma unroll
                for (int j = 0; j < 4; j++)
                    acc[i][j] = fmaf(xv[i], ee[j], acc[i][j]);
        }

        // ---- score & running top-2 (ascending code order => first-min tiebreak)
        const int cbase = chnk * CHUNK + tx * 4;
        #pragma unroll
        for (int j = 0; j < 4; j++) {
            float e2 = e2s[tx * 4 + j];
            #pragma unroll
            for (int i = 0; i < 8; i++) {
                float s = fmaf(-2.f, acc[i][j], e2);
                if (s < minv[i]) { min2[i] = minv[i]; minv[i] = s; mini[i] = cbase + j; }
                else if (s < min2[i]) { min2[i] = s; }
            }
        }
    }

    // ---- top-2 reduce over tx (lane bits 0..3), prefer lower index on ties ----
    #pragma unroll
    for (int off = 8; off >= 1; off >>= 1) {
        #pragma unroll
        for (int i = 0; i < 8; i++) {
            float ov = __shfl_xor_sync(0xffffffffu, minv[i], off);
            int   oi = __shfl_xor_sync(0xffffffffu, mini[i], off);
            float o2 = __shfl_xor_sync(0xffffffffu, min2[i], off);
            float hi = fmaxf(minv[i], ov);           // loser of the two top-1s
            min2[i] = fminf(fminf(min2[i], o2), hi);
            if (ov < minv[i] || (ov == minv[i] && oi < mini[i])) {
                minv[i] = ov; mini[i] = oi;
            }
        }
    }

    if (tx == 0) {
        float ls = 0.f;
        #pragma unroll
        for (int i = 0; i < 8; i++) {
            int p = ty * 8 + i;
            ridx[p] = mini[i];
            ls += minv[i] + x2s[p];       // ||x-e||^2 = min(e2-2xe) + x2
            if (min2[i] - minv[i] < MARGIN) {       // near-tie: exact re-check later
                int slot = atomicAdd(&g_fix_cnt, 1);
                if (slot < FIX_CAP) g_fix_list[slot] = pbase + p;
            }
        }
        rloss[ty] = ls;
    }
    __syncthreads();

    // ---- histogram + idx output ----
    if (t < PPC) {
        atomicAdd(&g_counts[ridx[t]], 1);
        out_idx[pbase + t] = (float)ridx[t];
    }
    if (t == 0) {
        float s = 0.f;
        #pragma unroll
        for (int i = 0; i < 16; i++) s += rloss[i];
        long long q = llrint((double)s * 1048576.0);   // fixed-point: deterministic
        atomicAdd(&g_loss_sum, (unsigned long long)q);
    }

    // ---- quantized output, channel-first, coalesced over pixels ----
    #pragma unroll
    for (int r = 0; r < 32; r++) {
        int e = r * 256 + t;     // 0..8191
        int c = e >> 7;          // /128
        int p = e & 127;
        out_xq[(b * CH + c) * HW + hw + p] = emb[ridx[p] * CH + c];
    }
}

// ---------------------------------------------------------------------------
// Fixup: exact (double) argmin for flagged near-tie tokens; patch outputs
// ---------------------------------------------------------------------------
__global__ __launch_bounds__(256) void vq_fixup(
        const float* __restrict__ x_in,
        const float* __restrict__ emb,
        float* __restrict__ out_xq,
        float* __restrict__ out_idx)
{
    __shared__ double xd[CH];
    __shared__ double rv[256];
    __shared__ int    rix[256];
    __shared__ int    oldi_s;

    const int t = threadIdx.x;
    int nfix = g_fix_cnt;
    if (nfix > FIX_CAP) nfix = FIX_CAP;

    for (int f = blockIdx.x; f < nfix; f += gridDim.x) {
        int p  = g_fix_list[f];
        int b  = p >> 12;          // / 4096
        int hw = p & 4095;

        if (t < CH) xd[t] = (double)x_in[(b * CH + t) * HW + hw];
        __syncthreads();

        double bm = 1e300; int bi = 0;
        #pragma unroll
        for (int j = 0; j < 4; j++) {
            int c = t * 4 + j;
            const float* e = emb + c * CH;
            double d = 0.0;
            #pragma unroll
            for (int k = 0; k < CH; k++) {
                double diff = xd[k] - (double)e[k];
                d += diff * diff;
            }
            if (d < bm) { bm = d; bi = c; }
        }
        rv[t] = bm; rix[t] = bi;
        __syncthreads();
        #pragma unroll
        for (int off = 128; off > 0; off >>= 1) {
            if (t < off) {
                if (rv[t + off] < rv[t] ||
                    (rv[t + off] == rv[t] && rix[t + off] < rix[t])) {
                    rv[t] = rv[t + off]; rix[t] = rix[t + off];
                }
            }
            __syncthreads();
        }
        int    newi = rix[0];
        double newd = rv[0];

        if (t == 0) oldi_s = (int)out_idx[p];
        __syncthreads();
        int oldi = oldi_s;

        if (newi != oldi) {
            if (t == 0) {
                // exact distance at old index for the loss delta
                double dold = 0.0;
                const float* e = emb + oldi * CH;
                #pragma unroll
                for (int k = 0; k < CH; k++) {
                    double diff = xd[k] - (double)e[k];
                    dold += diff * diff;
                }
                atomicAdd(&g_counts[oldi], -1);
                atomicAdd(&g_counts[newi],  1);
                long long dq = llrint((newd - dold) * 1048576.0);
                atomicAdd(&g_loss_sum, (unsigned long long)dq);  // signed wrap ok
                out_idx[p] = (float)newi;
            }
            if (t < CH) out_xq[(b * CH + t) * HW + hw] = emb[newi * CH + t];
        }
        __syncthreads();   // shared reuse across f iterations
    }
}

// ---------------------------------------------------------------------------
// Epilogue: vq_loss + perplexity
// ---------------------------------------------------------------------------
__global__ void vq_final(float* __restrict__ out_tail) {
    __shared__ float red[256];
    int t = threadIdx.x;
    float s = 0.f;
    for (int c = t; c < NCODE; c += 256) {
        float p = (float)g_counts[c] * (1.0f / (float)NPIX);
        s += p * logf(p + 1e-10f);
    }
    red[t] = s;
    __syncthreads();
    #pragma unroll
    for (int off = 128; off > 0; off >>= 1) {
        if (t < off) red[t] += red[t + off];
        __syncthreads();
    }
    if (t == 0) {
        double loss_sum = (double)(long long)g_loss_sum / 1048576.0;
        float e_loss = (float)(loss_sum / (double)((long long)NPIX * CH));
        out_tail[0] = 0.25f * e_loss;   // BETA * e_loss
        out_tail[1] = expf(-red[0]);    // perplexity
    }
}

// ---------------------------------------------------------------------------
extern "C" void kernel_launch(void* const* d_in, const int* in_sizes, int n_in,
                              void* d_out, int out_size) {
    const float* x_in = (const float*)d_in[0];
    const float* emb  = (const float*)d_in[1];
    float* out      = (float*)d_out;
    float* out_xq   = out;
    float* out_idx  = out + XQ_ELEMS;
    float* out_tail = out + XQ_ELEMS + IDX_ELEMS;

    const int smem_bytes = (CH * PPC + CH * ES_STRIDE) * (int)sizeof(float); // 50176
    cudaFuncSetAttribute(vq_main, cudaFuncAttributeMaxDynamicSharedMemorySize,
                         smem_bytes);

    vq_prep <<<(NCODE + 255) / 256, 256>>>(emb);
    vq_main <<<NPIX / PPC, 256, smem_bytes>>>(x_in, emb, out_xq, out_idx);
    vq_fixup<<<256, 256>>>(x_in, emb, out_xq, out_idx);
    vq_final<<<1, 256>>>(out_tail);
}

// round 6
// speedup vs baseline: 1.1759x; 1.1759x over previous
#include <cuda_runtime.h>
#include <cuda_bf16.h>
#include <cstdint>

// Problem constants (fixed shapes per reference setup_inputs)
#define BATCH    32
#define CH       64
#define HW       4096          // 64*64
#define NPIX     131072        // BATCH*HW
#define NCODE    1024
#define PPC      128           // pixels per CTA (= GEMM M)
#define BROWS    64            // codes per chunk (= GEMM N)
#define NCHK     (NCODE / BROWS)  // 16
#define KP       192           // split-K: A=[hi|hi|lo], B=[hi|lo|hi]
#define KSTEPS   (KP / 16)     // 12
#define ASTRIDE  200           // bf16 elems per A row (400B: 400%128=16 -> conflict-free)
#define BSTRIDE  200
#define MARGIN   1e-2f
#define FIX_CAP  32768

#define XQ_ELEMS  (NPIX * CH)  // 8388608
#define IDX_ELEMS NPIX         // 131072

#define A_BYTES   (PPC * ASTRIDE * 2)    // 51200
#define B_BYTES   (BROWS * BSTRIDE * 2)  // 25600
#define DYN_SMEM  (A_BYTES + 2 * B_BYTES)

// Scratch (device globals — no allocation allowed)
__device__ float              g_e2[NCODE];
__device__ int                g_counts[NCODE];
__device__ unsigned long long g_loss_sum;
__device__ int                g_fix_cnt;
__device__ int                g_fix_list[FIX_CAP];
__device__ __nv_bfloat16      g_Bpack[NCODE * KP];   // [code][k'] row-major

// ---------------------------------------------------------------------------
// SM80+-vintage PTX helpers (all supported on base sm_100)
// ---------------------------------------------------------------------------
__device__ __forceinline__ uint32_t smem_u32(const void* p) {
    uint32_t a;
    asm("{ .reg .u64 t; cvta.to.shared.u64 t, %1; cvt.u32.u64 %0, t; }"
        : "=r"(a) : "l"(p));
    return a;
}
__device__ __forceinline__ void ldsm_x4(uint32_t* r, uint32_t addr) {
    asm volatile("ldmatrix.sync.aligned.m8n8.x4.shared.b16 {%0,%1,%2,%3}, [%4];"
                 : "=r"(r[0]), "=r"(r[1]), "=r"(r[2]), "=r"(r[3]) : "r"(addr));
}
__device__ __forceinline__ void ldsm_x2(uint32_t* r, uint32_t addr) {
    asm volatile("ldmatrix.sync.aligned.m8n8.x2.shared.b16 {%0,%1}, [%2];"
                 : "=r"(r[0]), "=r"(r[1]) : "r"(addr));
}
__device__ __forceinline__ void mma_bf16(float* d, const uint32_t* a, const uint32_t* b) {
    asm volatile(
        "mma.sync.aligned.m16n8k16.row.col.f32.bf16.bf16.f32 "
        "{%0,%1,%2,%3}, {%4,%5,%6,%7}, {%8,%9}, {%0,%1,%2,%3};"
        : "+f"(d[0]), "+f"(d[1]), "+f"(d[2]), "+f"(d[3])
        : "r"(a[0]), "r"(a[1]), "r"(a[2]), "r"(a[3]), "r"(b[0]), "r"(b[1]));
}
#define CP_ASYNC16(dst, src) \
    asm volatile("cp.async.cg.shared.global [%0], [%1], 16;" :: "r"(dst), "l"(src))
#define CP_COMMIT() asm volatile("cp.async.commit_group;" ::: "memory")
#define CP_WAIT1()  asm volatile("cp.async.wait_group 1;" ::: "memory")
#define CP_WAIT0()  asm volatile("cp.async.wait_group 0;" ::: "memory")

// ---------------------------------------------------------------------------
// Prep A: ||e||^2 per code, zero accumulators
// ---------------------------------------------------------------------------
__global__ void vq_prep(const float* __restrict__ emb) {
    int c = blockIdx.x * blockDim.x + threadIdx.x;
    if (c < NCODE) {
        const float* row = emb + c * CH;
        float s = 0.f;
        #pragma unroll
        for (int k = 0; k < CH; k++) s = fmaf(row[k], row[k], s);
        g_e2[c]     = s;
        g_counts[c] = 0;
    }
    if (c == 0) { g_loss_sum = 0ull; g_fix_cnt = 0; }
}

// ---------------------------------------------------------------------------
// Prep B: pack codebook as [code][k'] bf16, k' = [e_hi(64) | e_lo(64) | e_hi(64)]
// ---------------------------------------------------------------------------
__global__ void vq_pack(const float* __restrict__ emb) {
    int c = blockIdx.x * blockDim.x + threadIdx.x;
    if (c >= NCODE) return;
    __nv_bfloat16* dst = g_Bpack + c * KP;
    for (int k = 0; k < CH; k++) {
        float x = emb[c * CH + k];
        __nv_bfloat16 hi = __float2bfloat16_rn(x);
        __nv_bfloat16 lo = __float2bfloat16_rn(x - __bfloat162float(hi));
        dst[k]       = hi;
        dst[64 + k]  = lo;
        dst[128 + k] = hi;
    }
}

// ---------------------------------------------------------------------------
// Main: HMMA (mma.sync bf16) distance GEMM, argmin fused on accumulators.
//   8 warps: warp_m = wid&3 (32 pixels), warp_n = wid>>2 (32 codes of chunk)
// ---------------------------------------------------------------------------
extern __shared__ char smem_dyn[];   // A[128][200] bf16 | B0 | B1

__global__ __launch_bounds__(256, 2) void vq_main(
        const float* __restrict__ x_in,
        const float* __restrict__ emb,
        float* __restrict__ out_xq,
        float* __restrict__ out_idx)
{
    __shared__ float e2s[NCODE];
    __shared__ float x2s[PPC];
    __shared__ int   ridx[PPC];
    __shared__ float sm_v1[PPC][2], sm_v2[PPC][2];
    __shared__ int   sm_ix[PPC][2];
    __shared__ unsigned long long s_loss;

    __nv_bfloat16* As = (__nv_bfloat16*)smem_dyn;
    const uint32_t As_u = smem_u32(smem_dyn);
    const uint32_t Bu[2] = { As_u + A_BYTES, As_u + A_BYTES + B_BYTES };

    const int t      = threadIdx.x;
    const int lane   = t & 31;
    const int wid    = t >> 5;
    const int warp_m = wid & 3;
    const int warp_n = wid >> 2;
    const int b      = blockIdx.x >> 5;
    const int hw     = (blockIdx.x & 31) * PPC;
    const int pbase  = blockIdx.x * PPC;

    if (t == 0) s_loss = 0ull;
    if (t < PPC) x2s[t] = 0.f;
    // e2 table (broadcast-heavy later)
    #pragma unroll
    for (int i = 0; i < 4; i++) e2s[i * 256 + t] = g_e2[i * 256 + t];
    __syncthreads();

    // ---- prefetch B chunk 0 ----
    {
        #pragma unroll
        for (int i = 0; i < 6; i++) {
            int seg = i * 256 + t;           // 1536 segs of 16B
            int row = seg / 24, off = seg % 24;
            CP_ASYNC16(Bu[0] + row * (BSTRIDE * 2) + off * 16,
                       (const char*)(g_Bpack + row * KP) + off * 16);
        }
        CP_COMMIT();
    }

    // ---- A tile: gmem [c][p] fp32 -> smem [p][k'] bf16 (hi|hi|lo) + x2 ----
    #pragma unroll
    for (int r = 0; r < 8; r++) {
        int e  = r * 256 + t;
        int c  = e >> 5;
        int p4 = (e & 31) * 4;
        float4 v = *(const float4*)(x_in + (b * CH + c) * HW + hw + p4);
        float xv[4] = {v.x, v.y, v.z, v.w};
        #pragma unroll
        for (int q = 0; q < 4; q++) {
            int p = p4 + q;
            float x = xv[q];
            __nv_bfloat16 hi = __float2bfloat16_rn(x);
            __nv_bfloat16 lo = __float2bfloat16_rn(x - __bfloat162float(hi));
            As[p * ASTRIDE + c]        = hi;
            As[p * ASTRIDE + 64 + c]   = hi;
            As[p * ASTRIDE + 128 + c]  = lo;
            atomicAdd(&x2s[p], x * x);
        }
    }
    __syncthreads();

    // ldmatrix base addresses (bytes)
    uint32_t a_base[2];
    #pragma unroll
    for (int i = 0; i < 2; i++)
        a_base[i] = As_u + (warp_m * 32 + i * 16 + (lane & 15)) * (ASTRIDE * 2)
                  + (lane >> 4) * 16;
    const uint32_t b_row_off = (warp_n * 32 + (lane & 7)) * (BSTRIDE * 2)
                             + ((lane >> 3) & 1) * 16;

    float minv[4], min2[4];
    int   mini[4];
    #pragma unroll
    for (int s = 0; s < 4; s++) { minv[s] = 3.4e38f; min2[s] = 3.4e38f; mini[s] = 0; }

    for (int chunk = 0; chunk < NCHK; chunk++) {
        const int buf = chunk & 1;
        // prefetch next chunk into other buffer
        if (chunk + 1 < NCHK) {
            #pragma unroll
            for (int i = 0; i < 6; i++) {
                int seg = i * 256 + t;
                int row = seg / 24, off = seg % 24;
                CP_ASYNC16(Bu[buf ^ 1] + row * (BSTRIDE * 2) + off * 16,
                           (const char*)(g_Bpack + ((chunk + 1) * BROWS + row) * KP) + off * 16);
            }
            CP_COMMIT();
            CP_WAIT1();     // current chunk's group complete
        } else {
            CP_WAIT0();
        }
        __syncthreads();

        // ---- GEMM: 32x32 per warp, K'=192 ----
        float acc[2][4][4];
        #pragma unroll
        for (int i = 0; i < 2; i++)
            #pragma unroll
            for (int j = 0; j < 4; j++)
                #pragma unroll
                for (int r = 0; r < 4; r++) acc[i][j][r] = 0.f;

        #pragma unroll
        for (int kk = 0; kk < KSTEPS; kk++) {
            uint32_t af[2][4], bf[4][2];
            #pragma unroll
            for (int i = 0; i < 2; i++) ldsm_x4(af[i], a_base[i] + kk * 32);
            #pragma unroll
            for (int j = 0; j < 4; j++)
                ldsm_x2(bf[j], Bu[buf] + b_row_off + j * 8 * (BSTRIDE * 2) + kk * 32);
            #pragma unroll
            for (int i = 0; i < 2; i++)
                #pragma unroll
                for (int j = 0; j < 4; j++)
                    mma_bf16(acc[i][j], af[i], bf[j]);
        }

        // ---- fused epilogue: score + top-2 on fragments ----
        #pragma unroll
        for (int j = 0; j < 4; j++) {
            const int cb = chunk * BROWS + warp_n * 32 + j * 8 + (lane & 3) * 2;
            const float e20 = e2s[cb], e21 = e2s[cb + 1];
            #pragma unroll
            for (int i = 0; i < 2; i++) {
                #pragma unroll
                for (int h = 0; h < 2; h++) {       // row half: rows r, r+8
                    const int sl = i * 2 + h;
                    float s0 = fmaf(-2.f, acc[i][j][h * 2], e20);
                    float s1 = fmaf(-2.f, acc[i][j][h * 2 + 1], e21);
                    if (s0 < minv[sl]) { min2[sl] = minv[sl]; minv[sl] = s0; mini[sl] = cb; }
                    else if (s0 < min2[sl]) min2[sl] = s0;
                    if (s1 < minv[sl]) { min2[sl] = minv[sl]; minv[sl] = s1; mini[sl] = cb + 1; }
                    else if (s1 < min2[sl]) min2[sl] = s1;
                }
            }
        }
        __syncthreads();   // done reading B buf before it is overwritten
    }

    // ---- reduce across the 4 lanes of each row group (xor 1, xor 2) ----
    #pragma unroll
    for (int off = 1; off <= 2; off <<= 1) {
        #pragma unroll
        for (int s = 0; s < 4; s++) {
            float ov = __shfl_xor_sync(0xffffffffu, minv[s], off);
            int   oi = __shfl_xor_sync(0xffffffffu, mini[s], off);
            float o2 = __shfl_xor_sync(0xffffffffu, min2[s], off);
            float hi = fmaxf(minv[s], ov);
            min2[s] = fminf(fminf(min2[s], o2), hi);
            if (ov < minv[s] || (ov == minv[s] && oi < mini[s])) {
                minv[s] = ov; mini[s] = oi;
            }
        }
    }
    if ((lane & 3) == 0) {
        #pragma unroll
        for (int s = 0; s < 4; s++) {
            int p = warp_m * 32 + (s >> 1) * 16 + (lane >> 2) + (s & 1) * 8;
            sm_v1[p][warp_n] = minv[s];
            sm_v2[p][warp_n] = min2[s];
            sm_ix[p][warp_n] = mini[s];
        }
    }
    __syncthreads();

    // ---- per-pixel combine of the two N-halves + outputs ----
    if (t < PPC) {
        float v1 = sm_v1[t][0], v2 = sm_v2[t][0];
        int   ix = sm_ix[t][0];
        float w1 = sm_v1[t][1], w2 = sm_v2[t][1];
        int   wx = sm_ix[t][1];
        float hi = fmaxf(v1, w1);
        float m2 = fminf(fminf(v2, w2), hi);
        if (w1 < v1 || (w1 == v1 && wx < ix)) { v1 = w1; ix = wx; }

        ridx[t] = ix;
        out_idx[pbase + t] = (float)ix;
        atomicAdd(&g_counts[ix], 1);
        if (m2 - v1 < MARGIN) {
            int slot = atomicAdd(&g_fix_cnt, 1);
            if (slot < FIX_CAP) g_fix_list[slot] = pbase + t;
        }
        long long q = llrint((double)(v1 + x2s[t]) * 1048576.0);
        atomicAdd(&s_loss, (unsigned long long)q);
    }
    __syncthreads();
    if (t == 0) atomicAdd(&g_loss_sum, s_loss);

    // ---- quantized output, channel-first, coalesced over pixels ----
    #pragma unroll
    for (int r = 0; r < 32; r++) {
        int e = r * 256 + t;
        int c = e >> 7;
        int p = e & 127;
        out_xq[(b * CH + c) * HW + hw + p] = emb[ridx[p] * CH + c];
    }
}

// ---------------------------------------------------------------------------
// Fixup: exact (double) argmin for flagged near-tie tokens; patch outputs
// ---------------------------------------------------------------------------
__global__ __launch_bounds__(256) void vq_fixup(
        const float* __restrict__ x_in,
        const float* __restrict__ emb,
        float* __restrict__ out_xq,
        float* __restrict__ out_idx)
{
    __shared__ double xd[CH];
    __shared__ double rv[256];
    __shared__ int    rix[256];
    __shared__ int    oldi_s;

    const int t = threadIdx.x;
    int nfix = g_fix_cnt;
    if (nfix > FIX_CAP) nfix = FIX_CAP;

    for (int f = blockIdx.x; f < nfix; f += gridDim.x) {
        int p  = g_fix_list[f];
        int b  = p >> 12;
        int hw = p & 4095;

        if (t < CH) xd[t] = (double)x_in[(b * CH + t) * HW + hw];
        __syncthreads();

        double bm = 1e300; int bi = 0;
        #pragma unroll
        for (int j = 0; j < 4; j++) {
            int c = t * 4 + j;
            const float* e = emb + c * CH;
            double d = 0.0;
            #pragma unroll
            for (int k = 0; k < CH; k++) {
                double diff = xd[k] - (double)e[k];
                d += diff * diff;
            }
            if (d < bm) { bm = d; bi = c; }
        }
        rv[t] = bm; rix[t] = bi;
        __syncthreads();
        #pragma unroll
        for (int off = 128; off > 0; off >>= 1) {
            if (t < off) {
                if (rv[t + off] < rv[t] ||
                    (rv[t + off] == rv[t] && rix[t + off] < rix[t])) {
                    rv[t] = rv[t + off]; rix[t] = rix[t + off];
                }
            }
            __syncthreads();
        }
        int    newi = rix[0];
        double newd = rv[0];

        if (t == 0) oldi_s = (int)out_idx[p];
        __syncthreads();
        int oldi = oldi_s;

        if (newi != oldi) {
            if (t == 0) {
                double dold = 0.0;
                const float* e = emb + oldi * CH;
                #pragma unroll
                for (int k = 0; k < CH; k++) {
                    double diff = xd[k] - (double)e[k];
                    dold += diff * diff;
                }
                atomicAdd(&g_counts[oldi], -1);
                atomicAdd(&g_counts[newi],  1);
                long long dq = llrint((newd - dold) * 1048576.0);
                atomicAdd(&g_loss_sum, (unsigned long long)dq);  // signed wrap ok
                out_idx[p] = (float)newi;
            }
            if (t < CH) out_xq[(b * CH + t) * HW + hw] = emb[newi * CH + t];
        }
        __syncthreads();
    }
}

// ---------------------------------------------------------------------------
// Epilogue: vq_loss + perplexity
// ---------------------------------------------------------------------------
__global__ void vq_final(float* __restrict__ out_tail) {
    __shared__ float red[256];
    int t = threadIdx.x;
    float s = 0.f;
    for (int c = t; c < NCODE; c += 256) {
        float p = (float)g_counts[c] * (1.0f / (float)NPIX);
        s += p * logf(p + 1e-10f);
    }
    red[t] = s;
    __syncthreads();
    #pragma unroll
    for (int off = 128; off > 0; off >>= 1) {
        if (t < off) red[t] += red[t + off];
        __syncthreads();
    }
    if (t == 0) {
        double loss_sum = (double)(long long)g_loss_sum / 1048576.0;
        float e_loss = (float)(loss_sum / (double)((long long)NPIX * CH));
        out_tail[0] = 0.25f * e_loss;   // BETA * e_loss
        out_tail[1] = expf(-red[0]);    // perplexity
    }
}

// ---------------------------------------------------------------------------
extern "C" void kernel_launch(void* const* d_in, const int* in_sizes, int n_in,
                              void* d_out, int out_size) {
    const float* x_in = (const float*)d_in[0];
    const float* emb  = (const float*)d_in[1];
    float* out      = (float*)d_out;
    float* out_xq   = out;
    float* out_idx  = out + XQ_ELEMS;
    float* out_tail = out + XQ_ELEMS + IDX_ELEMS;

    cudaFuncSetAttribute(vq_main, cudaFuncAttributeMaxDynamicSharedMemorySize,
                         DYN_SMEM);

    vq_prep <<<(NCODE + 255) / 256, 256>>>(emb);
    vq_pack <<<(NCODE + 255) / 256, 256>>>(emb);
    vq_main <<<NPIX / PPC, 256, DYN_SMEM>>>(x_in, emb, out_xq, out_idx);
    vq_fixup<<<256, 256>>>(x_in, emb, out_xq, out_idx);
    vq_final<<<1, 256>>>(out_tail);
}